// round 15
// baseline (speedup 1.0000x reference)
#include <cuda_runtime.h>
#include <cuda_bf16.h>
#include <math.h>
#include <stdint.h>

#define BB     16
#define CC     256
#define HW     6400
#define NHEADS 8
#define CPH    32

// ---------------- scratch (static device globals; no allocation) -------------
__device__ float g_A[BB*CC*HW];
__device__ float g_B[BB*CC*HW];
__device__ float g_C[BB*CC*HW];
__device__ float g_D[BB*CC*HW];
__device__ float g_E[BB*CC*HW];
__device__ __nv_bfloat16 g_Wi[CC*CC];
__device__ __nv_bfloat16 g_Wo[CC*CC];

// ================= helpers ===================================================
__device__ __forceinline__ uint32_t smem_to_u32(const void* p) {
    uint32_t a;
    asm("{ .reg .u64 t; cvta.to.shared.u64 t, %1; cvt.u32.u64 %0, t; }" : "=r"(a) : "l"(p));
    return a;
}
__device__ __forceinline__ uint32_t pack2(float x, float y) {
    __nv_bfloat162 b = __float22bfloat162_rn(make_float2(x, y));
    return *(uint32_t*)&b;
}
__device__ __forceinline__ uint32_t hadd2u(uint32_t a, uint32_t b) {
    __nv_bfloat162 x = *(__nv_bfloat162*)&a, y = *(__nv_bfloat162*)&b;
    __nv_bfloat162 r = __hadd2(x, y);
    return *(uint32_t*)&r;
}
__device__ __forceinline__ void ldm_x4(uint32_t& r0, uint32_t& r1, uint32_t& r2, uint32_t& r3,
                                       uint32_t addr) {
    asm volatile("ldmatrix.sync.aligned.m8n8.x4.shared.b16 {%0,%1,%2,%3}, [%4];"
                 : "=r"(r0), "=r"(r1), "=r"(r2), "=r"(r3) : "r"(addr));
}
__device__ __forceinline__ void ldm_x4_t(uint32_t& r0, uint32_t& r1, uint32_t& r2, uint32_t& r3,
                                         uint32_t addr) {
    asm volatile("ldmatrix.sync.aligned.m8n8.x4.trans.shared.b16 {%0,%1,%2,%3}, [%4];"
                 : "=r"(r0), "=r"(r1), "=r"(r2), "=r"(r3) : "r"(addr));
}
__device__ __forceinline__ void ldm_x2(uint32_t& r0, uint32_t& r1, uint32_t addr) {
    asm volatile("ldmatrix.sync.aligned.m8n8.x2.shared.b16 {%0,%1}, [%2];"
                 : "=r"(r0), "=r"(r1) : "r"(addr));
}
__device__ __forceinline__ void ldm_x2_t(uint32_t& r0, uint32_t& r1, uint32_t addr) {
    asm volatile("ldmatrix.sync.aligned.m8n8.x2.trans.shared.b16 {%0,%1}, [%2];"
                 : "=r"(r0), "=r"(r1) : "r"(addr));
}
__device__ __forceinline__ void mma16816(float* d, const uint32_t* a, const uint32_t* b) {
    asm volatile("mma.sync.aligned.m16n8k16.row.col.f32.bf16.bf16.f32 "
                 "{%0,%1,%2,%3}, {%4,%5,%6,%7}, {%8,%9}, {%0,%1,%2,%3};"
                 : "+f"(d[0]), "+f"(d[1]), "+f"(d[2]), "+f"(d[3])
                 : "r"(a[0]), "r"(a[1]), "r"(a[2]), "r"(a[3]), "r"(b[0]), "r"(b[1]));
}
#define CP16(dst, src) asm volatile("cp.async.cg.shared.global [%0], [%1], 16;" :: "r"(dst), "l"(src))
#define CPCOMMIT()     asm volatile("cp.async.commit_group;" ::: "memory")
#define CPWAIT0()      asm volatile("cp.async.wait_group 0;" ::: "memory")

// ---------------- weight convert: fp32 -> bf16 (once) ------------------------
__global__ __launch_bounds__(256) void wconv_kernel(
    const float* __restrict__ w_in, const float* __restrict__ w_out,
    __nv_bfloat16* __restrict__ wi, __nv_bfloat16* __restrict__ wo)
{
    int i = blockIdx.x * 256 + threadIdx.x;     // 16384 threads, 4 elems each
    float4 a = ((const float4*)w_in)[i];
    uint2 u;
    u.x = pack2(a.x, a.y); u.y = pack2(a.z, a.w);
    ((uint2*)wi)[i] = u;
    float4 b = ((const float4*)w_out)[i];
    uint2 v;
    v.x = pack2(b.x, b.y); v.y = pack2(b.z, b.w);
    ((uint2*)wo)[i] = v;
}

// ---------------- LayerNorm, float4 per thread (bf16 out) --------------------
__global__ __launch_bounds__(64) void ln_kernel(const float* __restrict__ x,
                                                const float* __restrict__ gam,
                                                const float* __restrict__ bet,
                                                __nv_bfloat16* __restrict__ xn)
{
    int g  = blockIdx.x * 64 + threadIdx.x;    // 0..25599 (4-pixel groups)
    int b  = g / 1600;
    int pl = (g - b * 1600) * 4;
    const float* xb = x + b * CC * HW + pl;
    float4 s  = make_float4(0.f, 0.f, 0.f, 0.f);
    float4 s2 = make_float4(0.f, 0.f, 0.f, 0.f);
    #pragma unroll 8
    for (int c = 0; c < CC; c++) {
        float4 v = *(const float4*)(xb + c * HW);
        s.x += v.x; s.y += v.y; s.z += v.z; s.w += v.w;
        s2.x = fmaf(v.x, v.x, s2.x); s2.y = fmaf(v.y, v.y, s2.y);
        s2.z = fmaf(v.z, v.z, s2.z); s2.w = fmaf(v.w, v.w, s2.w);
    }
    const float ic = 1.f / CC;
    float4 mu = make_float4(s.x*ic, s.y*ic, s.z*ic, s.w*ic);
    float4 iv;
    iv.x = rsqrtf(s2.x*ic - mu.x*mu.x + 1e-5f);
    iv.y = rsqrtf(s2.y*ic - mu.y*mu.y + 1e-5f);
    iv.z = rsqrtf(s2.z*ic - mu.z*mu.z + 1e-5f);
    iv.w = rsqrtf(s2.w*ic - mu.w*mu.w + 1e-5f);
    __nv_bfloat16* ob = xn + b * CC * HW + pl;
    #pragma unroll 8
    for (int c = 0; c < CC; c++) {
        float4 v = *(const float4*)(xb + c * HW);
        float gm = gam[c], bt = bet[c];
        uint2 u;
        u.x = pack2((v.x - mu.x) * iv.x * gm + bt, (v.y - mu.y) * iv.y * gm + bt);
        u.y = pack2((v.z - mu.z) * iv.z * gm + bt, (v.w - mu.w) * iv.w * gm + bt);
        *(uint2*)(ob + c * HW) = u;
    }
}

// ---------------- fused depthwise, both dirs, bf16 HFMA2 2-wide --------------
__global__ __launch_bounds__(256) void dw_kernel(
    const __nv_bfloat16* __restrict__ xn,
    const float* __restrict__ wx7,  const float* __restrict__ bx7,
    const float* __restrict__ wx11, const float* __restrict__ bx11,
    const float* __restrict__ wx21, const float* __restrict__ bx21,
    const float* __restrict__ wy7,  const float* __restrict__ by7,
    const float* __restrict__ wy11, const float* __restrict__ by11,
    const float* __restrict__ wy21, const float* __restrict__ by21,
    __nv_bfloat16* __restrict__ dstX, __nv_bfloat16* __restrict__ dstY)
{
    __shared__ uint32_t pad[4000];
    __shared__ __nv_bfloat162 coef2[21];
    __shared__ float biasv;
    const int tid = threadIdx.x;
    const int dir = (blockIdx.x >= BB*CC) ? 1 : 0;
    const int bc  = blockIdx.x - dir * BB * CC;
    const int c   = bc & (CC - 1);
    const float* w7  = dir ? wy7  : wx7;
    const float* w11 = dir ? wy11 : wx11;
    const float* w21 = dir ? wy21 : wx21;
    for (int i = tid; i < 4000; i += 256) pad[i] = 0;
    if (tid < 21) {
        int t = tid - 10;
        float v = w21[c*21 + t + 10];
        if (t >= -5 && t <= 5) v += w11[c*11 + t + 5];
        if (t >= -3 && t <= 3) v += w7 [c*7  + t + 3];
        coef2[tid] = __float2bfloat162_rn(v);
    }
    if (tid == 0) {
        biasv = (dir ? (by7[c] + by11[c] + by21[c])
                     : (bx7[c] + bx11[c] + bx21[c]));
    }
    __syncthreads();
    const uint32_t* src32 = (const uint32_t*)(xn + bc * HW);
    if (dir == 0) {
        for (int i = tid; i < 1600; i += 256) {
            int h2 = i / 40, wp2 = i - h2 * 40;
            uint32_t a01 = src32[(2*h2)*40 + wp2];
            uint32_t b01 = src32[(2*h2+1)*40 + wp2];
            pad[h2*100 + 10 + 2*wp2] = __byte_perm(a01, b01, 0x5410);
            pad[h2*100 + 11 + 2*wp2] = __byte_perm(a01, b01, 0x7632);
        }
    } else {
        for (int i = tid; i < 3200; i += 256) {
            int h = i / 40, w2 = i - h * 40;
            pad[(h + 10)*40 + w2] = src32[i];
        }
    }
    __syncthreads();
    const __nv_bfloat162 bias2 = __float2bfloat162_rn(biasv);
    const __nv_bfloat162 z2    = __float2bfloat162_rn(0.f);
    uint32_t* dst32 = (uint32_t*)((dir ? dstY : dstX) + bc * HW);
    for (int i = tid; i < 1600; i += 256) {
        int h2 = i / 40, w2 = i - h2 * 40;
        uint32_t win[22];
        if (dir == 0) {
            #pragma unroll
            for (int t = 0; t < 22; t++) win[t] = pad[h2*100 + 2*w2 + t];
        } else {
            #pragma unroll
            for (int t = 0; t < 22; t++) win[t] = pad[(2*h2 + t)*40 + w2];
        }
        __nv_bfloat162 ae = bias2, ao = z2, be = bias2, bo = z2;
        #pragma unroll
        for (int t = 0; t < 21; t++) {
            __nv_bfloat162 w0 = *(__nv_bfloat162*)&win[t];
            __nv_bfloat162 w1 = *(__nv_bfloat162*)&win[t + 1];
            if (t & 1) { ao = __hfma2(coef2[t], w0, ao); bo = __hfma2(coef2[t], w1, bo); }
            else       { ae = __hfma2(coef2[t], w0, ae); be = __hfma2(coef2[t], w1, be); }
        }
        __nv_bfloat162 A2 = __hadd2(ae, ao);
        __nv_bfloat162 B2 = __hadd2(be, bo);
        uint32_t uA = *(uint32_t*)&A2, uB = *(uint32_t*)&B2;
        if (dir == 0) {
            dst32[(2*h2)*40 + w2]   = __byte_perm(uA, uB, 0x5410);
            dst32[(2*h2+1)*40 + w2] = __byte_perm(uA, uB, 0x7632);
        } else {
            dst32[(2*h2)*40 + w2]   = uA;
            dst32[(2*h2+1)*40 + w2] = uB;
        }
    }
}

// ====== bf16 GEMM, cp.async weights + double-buffered A, merged inputs =======
#define GSMEM_BF (64*1024 + 2*16*1024)

__global__ __launch_bounds__(256) void gemm_bf(
    const __nv_bfloat16* __restrict__ Wb,
    const __nv_bfloat16* __restrict__ Xa, const __nv_bfloat16* __restrict__ Xb,
    const float* __restrict__ bias,
    __nv_bfloat16* __restrict__ Oa, __nv_bfloat16* __restrict__ Ob)
{
    extern __shared__ char smem[];
    char* Bs = smem;
    const uint32_t Bs32 = smem_to_u32(Bs);
    const uint32_t As32 = smem_to_u32(smem + 65536);
    const int tid = threadIdx.x, wid = tid >> 5, lane = tid & 31;
    const int wm = wid >> 1, wn = wid & 1;
    const int p0 = blockIdx.x * 128, o0 = blockIdx.y * 128;
    const int sel = blockIdx.z >> 4;
    const long xbase = (long)(blockIdx.z & 15) * (CC * HW);
    const __nv_bfloat16* X = sel ? Xb : Xa;
    __nv_bfloat16* out     = sel ? Ob : Oa;

    // weight fill via cp.async (merged into first commit group)
    #pragma unroll
    for (int it = 0; it < 16; it++) {
        int idx = tid + it * 256;
        int n = idx >> 5, kc = idx & 31;
        CP16(Bs32 + n * 512 + ((kc ^ (n & 7)) << 4), Wb + (o0 + n) * CC + kc * 8);
    }

    float acc[2][8][4];
    #pragma unroll
    for (int i = 0; i < 2; i++)
        #pragma unroll
        for (int j = 0; j < 8; j++)
            #pragma unroll
            for (int t = 0; t < 4; t++) acc[i][j][t] = 0.f;

    auto fillA = [&](int ch, int buf) {
        #pragma unroll
        for (int it = 0; it < 4; it++) {
            int idx = tid + it * 256;
            int k = idx >> 4, cm = idx & 15;
            const __nv_bfloat16* src = X + xbase + (long)(ch * 64 + k) * HW + p0 + cm * 8;
            uint32_t dst = As32 + buf * 16384 + k * 256 + ((cm ^ (k & 7)) << 4);
            CP16(dst, src);
        }
        CPCOMMIT();
    };

    fillA(0, 0);   // commits weights + A chunk 0
    for (int ch = 0; ch < 4; ch++) {
        CPWAIT0();
        __syncthreads();
        if (ch < 3) fillA(ch + 1, (ch + 1) & 1);
        const uint32_t Ab = As32 + (ch & 1) * 16384;
        #pragma unroll
        for (int ks = 0; ks < 4; ks++) {
            uint32_t a[2][4];
            #pragma unroll
            for (int am = 0; am < 2; am++) {
                int krow = ks * 16 + (lane & 7) + ((lane >> 4) << 3);
                int cm   = (wm * 32 + am * 16) / 8 + ((lane >> 3) & 1);
                ldm_x4_t(a[am][0], a[am][1], a[am][2], a[am][3],
                         Ab + krow * 256 + ((cm ^ (krow & 7)) << 4));
            }
            uint32_t b[4][4];
            #pragma unroll
            for (int bp = 0; bp < 4; bp++) {
                int n  = wn * 64 + bp * 16 + (lane & 15);
                int kc = ch * 8 + ks * 2 + (lane >> 4);
                ldm_x4(b[bp][0], b[bp][1], b[bp][2], b[bp][3],
                       Bs32 + n * 512 + ((kc ^ (n & 7)) << 4));
            }
            #pragma unroll
            for (int am = 0; am < 2; am++)
                #pragma unroll
                for (int an = 0; an < 8; an++) {
                    uint32_t bb[2] = { b[an >> 1][an & 1], b[an >> 1][(an & 1) + 2] };
                    mma16816(acc[am][an], a[am], bb);
                }
        }
    }

    __syncthreads();
    #pragma unroll
    for (int am = 0; am < 2; am++) {
        int m = wm * 32 + am * 16 + (lane >> 2);
        #pragma unroll
        for (int an = 0; an < 8; an++) {
            int nl = wn * 64 + an * 8 + (lane & 3) * 2;
            float b0 = bias[o0 + nl], b1 = bias[o0 + nl + 1];
            *(__nv_bfloat16*)(Bs + nl * 256 + m * 2)             = __float2bfloat16(acc[am][an][0] + b0);
            *(__nv_bfloat16*)(Bs + (nl + 1) * 256 + m * 2)       = __float2bfloat16(acc[am][an][1] + b1);
            *(__nv_bfloat16*)(Bs + nl * 256 + (m + 8) * 2)       = __float2bfloat16(acc[am][an][2] + b0);
            *(__nv_bfloat16*)(Bs + (nl + 1) * 256 + (m + 8) * 2) = __float2bfloat16(acc[am][an][3] + b1);
        }
    }
    __syncthreads();
    #pragma unroll
    for (int it = 0; it < 32; it++) {
        int idx = tid + it * 256;
        int n = idx >> 6, mu = idx & 63;
        uint32_t u = *(uint32_t*)(Bs + n * 256 + mu * 4);
        *(uint32_t*)(out + xbase + (long)(o0 + n) * HW + p0 + 2 * mu) = u;
    }
}

// ====== final GEMM: out = W@(X+X2) + 2b + resid, cp.async weights ============
#define GSMEM_OUT (64*1024 + 32*1024)

__global__ __launch_bounds__(256) void gemm_out(
    const __nv_bfloat16* __restrict__ Wb, const __nv_bfloat16* __restrict__ X,
    const __nv_bfloat16* __restrict__ X2,
    const float* __restrict__ bias, const float* __restrict__ resid,
    float* __restrict__ out)
{
    extern __shared__ char smem[];
    char* Bs = smem;
    const uint32_t Bs32 = smem_to_u32(Bs);
    const uint32_t As32 = smem_to_u32(smem + 65536);
    const int tid = threadIdx.x, wid = tid >> 5, lane = tid & 31;
    const int wm = wid >> 1, wn = wid & 1;
    const int p0 = blockIdx.x * 128, o0 = blockIdx.y * 128;
    const long xbase = (long)blockIdx.z * (CC * HW);

    #pragma unroll
    for (int it = 0; it < 16; it++) {
        int idx = tid + it * 256;
        int n = idx >> 5, kc = idx & 31;
        CP16(Bs32 + n * 512 + ((kc ^ (n & 7)) << 4), Wb + (o0 + n) * CC + kc * 8);
    }

    float acc[2][8][4];
    #pragma unroll
    for (int i = 0; i < 2; i++)
        #pragma unroll
        for (int j = 0; j < 8; j++)
            #pragma unroll
            for (int t = 0; t < 4; t++) acc[i][j][t] = 0.f;

    auto fillA = [&](int ch, int buf) {
        #pragma unroll
        for (int it = 0; it < 2; it++) {
            int idx = tid + it * 256;
            int k = idx >> 4, cm = idx & 15;
            long off = xbase + (long)(ch * 32 + k) * HW + p0 + cm * 8;
            uint32_t dst = As32 + buf * 16384 + k * 256 + ((cm ^ (k & 7)) << 4);
            CP16(dst, X + off);
            CP16(dst + 8192, X2 + off);
        }
        CPCOMMIT();
    };

    fillA(0, 0);
    for (int ch = 0; ch < 8; ch++) {
        CPWAIT0();
        __syncthreads();
        if (ch < 7) fillA(ch + 1, (ch + 1) & 1);
        const uint32_t Ab = As32 + (ch & 1) * 16384;
        #pragma unroll
        for (int ks = 0; ks < 2; ks++) {
            uint32_t a[2][4];
            #pragma unroll
            for (int am = 0; am < 2; am++) {
                int krow = ks * 16 + (lane & 7) + ((lane >> 4) << 3);
                int cm   = (wm * 32 + am * 16) / 8 + ((lane >> 3) & 1);
                uint32_t addr = Ab + krow * 256 + ((cm ^ (krow & 7)) << 4);
                uint32_t p0r, p1r, p2r, p3r, q0r, q1r, q2r, q3r;
                ldm_x4_t(p0r, p1r, p2r, p3r, addr);
                ldm_x4_t(q0r, q1r, q2r, q3r, addr + 8192);
                a[am][0] = hadd2u(p0r, q0r);
                a[am][1] = hadd2u(p1r, q1r);
                a[am][2] = hadd2u(p2r, q2r);
                a[am][3] = hadd2u(p3r, q3r);
            }
            uint32_t b[4][4];
            #pragma unroll
            for (int bp = 0; bp < 4; bp++) {
                int n  = wn * 64 + bp * 16 + (lane & 15);
                int kc = ch * 4 + ks * 2 + (lane >> 4);
                ldm_x4(b[bp][0], b[bp][1], b[bp][2], b[bp][3],
                       Bs32 + n * 512 + ((kc ^ (n & 7)) << 4));
            }
            #pragma unroll
            for (int am = 0; am < 2; am++)
                #pragma unroll
                for (int an = 0; an < 8; an++) {
                    uint32_t bb[2] = { b[an >> 1][an & 1], b[an >> 1][(an & 1) + 2] };
                    mma16816(acc[am][an], a[am], bb);
                }
        }
    }

    #pragma unroll
    for (int am = 0; am < 2; am++) {
        int m = wm * 32 + am * 16 + (lane >> 2);
        #pragma unroll
        for (int an = 0; an < 8; an++) {
            int n = o0 + wn * 64 + an * 8 + (lane & 3) * 2;
            float b0 = bias[n] * 2.f, b1 = bias[n + 1] * 2.f;
            long a00 = xbase + (long)n * HW + p0 + m;
            out[a00]          = acc[am][an][0] + b0 + resid[a00];
            out[a00 + HW]     = acc[am][an][1] + b1 + resid[a00 + HW];
            out[a00 + 8]      = acc[am][an][2] + b0 + resid[a00 + 8];
            out[a00 + HW + 8] = acc[am][an][3] + b1 + resid[a00 + HW + 8];
        }
    }
}

// ======== cross-axis attention: native-layout cp.async staging ===============
#define FPB 176
#define OFF_TK 28160
#define OFF_PS 56320
#define OFF_GM 70400
#define OFF_RQ 96320
#define OFF_RK 96640
#define OFF_PART 96960
#define ATTN2_SMEM 98240

__global__ __launch_bounds__(320, 2) void attn_kernel(
    const __nv_bfloat16* __restrict__ fx, const __nv_bfloat16* __restrict__ fy,
    __nv_bfloat16* __restrict__ outx, __nv_bfloat16* __restrict__ outy)
{
    extern __shared__ char sm2[];
    float* Gm = (float*)(sm2 + OFF_GM);
    float* rq = (float*)(sm2 + OFF_RQ);
    float* rk = (float*)(sm2 + OFF_RK);
    float* part = (float*)(sm2 + OFF_PART);
    const uint32_t tq32 = smem_to_u32(sm2);
    const uint32_t tk32 = tq32 + OFF_TK;
    const uint32_t ps32 = tq32 + OFF_PS;

    const int axis = blockIdx.x >> 7;
    const int bh   = blockIdx.x & 127;
    const int cbase = (bh >> 3) * (CC*HW) + (bh & 7) * (CPH*HW);
    const __nv_bfloat16* Qb = (axis ? fx : fy) + cbase;
    const __nv_bfloat16* Kb = (axis ? fy : fx) + cbase;
    __nv_bfloat16* outb     = (axis ? outy : outx) + cbase;
    const int tid  = threadIdx.x;
    const int wid  = tid >> 5, lane = tid & 31;
    const int mt   = wid >> 1, nh = wid & 1;

    auto fill = [&](int c, int b) {
        const __nv_bfloat16* qc = Qb + c*HW;
        const __nv_bfloat16* kc = Kb + c*HW;
        uint32_t dq = tq32 + b * 14080;
        uint32_t dk = tk32 + b * 14080;
        #pragma unroll
        for (int it = 0; it < 5; it++) {
            int idx = tid + it * 320;
            int pl  = (idx >= 800);
            int j   = idx - pl * 800;
            int r = j / 10, cj = j - r * 10;
            const __nv_bfloat16* s = (pl ? kc : qc) + r * 80 + cj * 8;
            uint32_t d = (pl ? dk : dq) + r * FPB + cj * 16;
            CP16(d, s);
        }
        CPCOMMIT();
    };

    auto loadB = [&](uint32_t tb, int ks, bool tr, uint32_t* bA, uint32_t* bB, uint32_t* bC) {
        if (!tr) {
            {
                int row = nh*40 + (lane & 15);
                ldm_x4(bA[0], bA[1], bA[2], bA[3], tb + row*FPB + ks*32 + ((lane >> 4) << 4));
            }
            {
                int row = nh*40 + 16 + (lane & 15);
                ldm_x4(bB[0], bB[1], bB[2], bB[3], tb + row*FPB + ks*32 + ((lane >> 4) << 4));
            }
            {
                int row = nh*40 + 32 + (lane & 7);
                ldm_x2(bC[0], bC[1], tb + row*FPB + ks*32 + (((lane >> 3) & 1) << 4));
            }
        } else {
            int krow = ks*16 + (lane & 7) + ((lane >> 4) << 3);
            {
                int nc = nh*5 + ((lane >> 3) & 1);
                ldm_x4_t(bA[0], bA[1], bA[2], bA[3], tb + krow*FPB + (nc << 4));
            }
            {
                int nc = nh*5 + 2 + ((lane >> 3) & 1);
                ldm_x4_t(bB[0], bB[1], bB[2], bB[3], tb + krow*FPB + (nc << 4));
            }
            {
                int kr2 = ks*16 + (lane & 7) + (((lane >> 3) & 1) << 3);
                int nc = nh*5 + 4;
                ldm_x2_t(bC[0], bC[1], tb + kr2*FPB + (nc << 4));
            }
        }
    };

    float acc[5][4];
    #pragma unroll
    for (int j = 0; j < 5; j++)
        #pragma unroll
        for (int t = 0; t < 4; t++) acc[j][t] = 0.f;
    float nss = 0.f;

    // ================= Phase 1: raw Gram + fused sumsq (all 320 threads) =====
    const int seqp = tid >> 1;          // 0..159
    const int shalf = tid & 1;
    fill(0, 0);
    for (int c = 0; c < CPH; c++) {
        const int b = c & 1;
        CPWAIT0();
        __syncthreads();
        if (c < CPH-1) fill(c + 1, b ^ 1);
        const uint32_t qb = tq32 + b * 14080;
        const uint32_t kb = tk32 + b * 14080;
        {
            const char* pb = (char*)sm2 + ((seqp < 80) ? b*14080 : OFF_TK + b*14080);
            int sp = (seqp < 80) ? seqp : seqp - 80;
            float s = 0.f;
            if (axis == 0) {
                const char* rowp = pb + sp * FPB + shalf * 80;
                #pragma unroll
                for (int u = 0; u < 20; u++) {
                    __nv_bfloat162 h2 = *(const __nv_bfloat162*)(rowp + 4*u);
                    float2 f2 = __bfloat1622float2(h2);
                    s = fmaf(f2.x, f2.x, fmaf(f2.y, f2.y, s));
                }
            } else {
                #pragma unroll 8
                for (int rr = shalf*40; rr < shalf*40 + 40; rr++) {
                    float v = __bfloat162float(*(const __nv_bfloat16*)(pb + rr*FPB + sp*2));
                    s = fmaf(v, v, s);
                }
            }
            nss += s;
        }
        #pragma unroll
        for (int ks = 0; ks < 5; ks++) {
            uint32_t a[4];
            if (axis == 0) {
                int row = mt*16 + (lane & 15);
                ldm_x4(a[0], a[1], a[2], a[3], qb + row*FPB + ks*32 + ((lane >> 4) << 4));
            } else {
                int krow = ks*16 + (lane & 7) + ((lane >> 4) << 3);
                int mc   = mt*2 + ((lane >> 3) & 1);
                ldm_x4_t(a[0], a[1], a[2], a[3], qb + krow*FPB + (mc << 4));
            }
            uint32_t bA[4], bB[4], bC[2];
            loadB(kb, ks, axis == 1, bA, bB, bC);
            { uint32_t bb[2] = { bA[0], bA[2] }; mma16816(acc[0], a, bb); }
            { uint32_t bb[2] = { bA[1], bA[3] }; mma16816(acc[1], a, bb); }
            { uint32_t bb[2] = { bB[0], bB[2] }; mma16816(acc[2], a, bb); }
            { uint32_t bb[2] = { bB[1], bB[3] }; mma16816(acc[3], a, bb); }
            { uint32_t bb[2] = { bC[0], bC[1] }; mma16816(acc[4], a, bb); }
        }
    }
    __syncthreads();
    part[tid] = nss;
    __syncthreads();
    if (tid < 160) {
        float s = part[2*tid] + part[2*tid + 1];
        float inv = 1.f / fmaxf(sqrtf(s), 1e-12f);
        if (tid < 80) rq[tid] = inv; else rk[tid - 80] = inv;
    }
    __syncthreads();
    {
        int row  = mt*16 + (lane >> 2);
        int colb = nh*40 + (lane & 3) * 2;
        float r0 = rq[row], r1 = rq[row + 8];
        #pragma unroll
        for (int j = 0; j < 5; j++) {
            int col = colb + j*8;
            float k0 = rk[col], k1 = rk[col + 1];
            Gm[row*81 + col]       = acc[j][0] * r0 * k0;
            Gm[row*81 + col + 1]   = acc[j][1] * r0 * k1;
            Gm[(row+8)*81 + col]   = acc[j][2] * r1 * k0;
            Gm[(row+8)*81 + col+1] = acc[j][3] * r1 * k1;
        }
    }
    __syncthreads();
    // ================= Phase 2: softmax rows =================
    if (tid < 80) {
        float* row = Gm + tid*81;
        float mx = -3.0e38f;
        for (int m = 0; m < 80; m++) mx = fmaxf(mx, row[m]);
        float s = 0.f;
        for (int m = 0; m < 80; m++) { float e = expf(row[m] - mx); row[m] = e; s += e; }
        float is = 1.f / s;
        for (int m = 0; m < 80; m++) row[m] *= is;
    }
    __syncthreads();
    #pragma unroll
    for (int it = 0; it < 10; it++) {
        int p = tid + it * 320;
        int n = p / 40, mp = p - n * 40;
        *(uint32_t*)(sm2 + OFF_PS + n*FPB + 4*mp) = pack2(Gm[n*81 + 2*mp], Gm[n*81 + 2*mp + 1]);
    }
    __syncthreads();
    uint32_t aP[5][4];
    #pragma unroll
    for (int ks = 0; ks < 5; ks++) {
        int row = mt*16 + (lane & 15);
        ldm_x4(aP[ks][0], aP[ks][1], aP[ks][2], aP[ks][3],
               ps32 + row*FPB + ks*32 + ((lane >> 4) << 4));
    }

    // ================= Phase 3: out = P@V + q*rq =================
    fill(0, 0);
    for (int c = 0; c < CPH; c++) {
        const int b = c & 1;
        CPWAIT0();
        __syncthreads();
        if (c < CPH-1) fill(c + 1, b ^ 1);
        const uint32_t kb = tk32 + b * 14080;
        const char* qsm = sm2 + b * 14080;
        float o[5][4];
        #pragma unroll
        for (int j = 0; j < 5; j++)
            #pragma unroll
            for (int t = 0; t < 4; t++) o[j][t] = 0.f;
        #pragma unroll
        for (int ks = 0; ks < 5; ks++) {
            uint32_t bA[4], bB[4], bC[2];
            loadB(kb, ks, axis == 0, bA, bB, bC);
            { uint32_t bb[2] = { bA[0], bA[2] }; mma16816(o[0], aP[ks], bb); }
            { uint32_t bb[2] = { bA[1], bA[3] }; mma16816(o[1], aP[ks], bb); }
            { uint32_t bb[2] = { bB[0], bB[2] }; mma16816(o[2], aP[ks], bb); }
            { uint32_t bb[2] = { bB[1], bB[3] }; mma16816(o[3], aP[ks], bb); }
            { uint32_t bb[2] = { bC[0], bC[1] }; mma16816(o[4], aP[ks], bb); }
        }
        __nv_bfloat16* ob = outb + c*HW;
        int row  = mt*16 + (lane >> 2);
        int colb = nh*40 + (lane & 3) * 2;
        #pragma unroll
        for (int j = 0; j < 5; j++) {
            int col = colb + j*8;
            #pragma unroll
            for (int half = 0; half < 2; half++) {
                int rr = row + 8*half;
                float rqi = rq[rr];
                float q0, q1;
                if (axis == 0) {
                    __nv_bfloat162 q2 = *(const __nv_bfloat162*)(qsm + rr*FPB + col*2);
                    float2 qf = __bfloat1622float2(q2);
                    q0 = qf.x; q1 = qf.y;
                } else {
                    q0 = __bfloat162float(*(const __nv_bfloat16*)(qsm + col*FPB + rr*2));
                    q1 = __bfloat162float(*(const __nv_bfloat16*)(qsm + (col+1)*FPB + rr*2));
                }
                float v0 = o[j][2*half]     + q0 * rqi;
                float v1 = o[j][2*half + 1] + q1 * rqi;
                if (axis == 0) {
                    *(uint32_t*)(ob + rr*80 + col) = pack2(v0, v1);
                } else {
                    ob[col*80 + rr]       = __float2bfloat16(v0);
                    ob[(col+1)*80 + rr]   = __float2bfloat16(v1);
                }
            }
        }
    }
}

// ---------------- launch -----------------------------------------------------
extern "C" void kernel_launch(void* const* d_in, const int* in_sizes, int n_in,
                              void* d_out, int out_size)
{
    const float* x    = (const float*)d_in[0];
    const float* ln_g = (const float*)d_in[1];
    const float* ln_b = (const float*)d_in[2];
    const float* w_in = (const float*)d_in[3];
    const float* b_in = (const float*)d_in[4];
    const float* w_out= (const float*)d_in[5];
    const float* b_out= (const float*)d_in[6];
    const float* wx7  = (const float*)d_in[7];
    const float* bx7  = (const float*)d_in[8];
    const float* wx11 = (const float*)d_in[9];
    const float* bx11 = (const float*)d_in[10];
    const float* wx21 = (const float*)d_in[11];
    const float* bx21 = (const float*)d_in[12];
    const float* wy7  = (const float*)d_in[13];
    const float* by7  = (const float*)d_in[14];
    const float* wy11 = (const float*)d_in[15];
    const float* by11 = (const float*)d_in[16];
    const float* wy21 = (const float*)d_in[17];
    const float* by21 = (const float*)d_in[18];
    float* out = (float*)d_out;

    float *pA, *pB, *pC, *pD, *pE;
    cudaGetSymbolAddress((void**)&pA, g_A);
    cudaGetSymbolAddress((void**)&pB, g_B);
    cudaGetSymbolAddress((void**)&pC, g_C);
    cudaGetSymbolAddress((void**)&pD, g_D);
    cudaGetSymbolAddress((void**)&pE, g_E);
    __nv_bfloat16 *hWi, *hWo;
    cudaGetSymbolAddress((void**)&hWi, g_Wi);
    cudaGetSymbolAddress((void**)&hWo, g_Wo);
    __nv_bfloat16* hA = (__nv_bfloat16*)pA;
    __nv_bfloat16* hB = (__nv_bfloat16*)pB;
    __nv_bfloat16* hC = (__nv_bfloat16*)pC;
    __nv_bfloat16* hD = (__nv_bfloat16*)pD;
    __nv_bfloat16* hE = (__nv_bfloat16*)pE;

    cudaFuncSetAttribute(attn_kernel, cudaFuncAttributeMaxDynamicSharedMemorySize, ATTN2_SMEM);
    cudaFuncSetAttribute(gemm_bf,  cudaFuncAttributeMaxDynamicSharedMemorySize, GSMEM_BF);
    cudaFuncSetAttribute(gemm_out, cudaFuncAttributeMaxDynamicSharedMemorySize, GSMEM_OUT);

    // 0) weights fp32 -> bf16 (once per call; tiny)
    wconv_kernel<<<64, 256>>>(w_in, w_out, hWi, hWo);
    // 1) LayerNorm: x -> A (bf16 xn)
    ln_kernel<<<400, 64>>>(x, ln_g, ln_b, hA);
    // 2) depthwise (both dirs): A -> B (bf16 sx), C (bf16 sy)
    dw_kernel<<<2*BB*CC, 256>>>(hA, wx7, bx7, wx11, bx11, wx21, bx21,
                                wy7, by7, wy11, by11, wy21, by21, hB, hC);
    // 3) pointwise w_in merged: B->D (fx), C->E (fy)
    dim3 gg(HW/128, CC/128, 2*BB);
    gemm_bf<<<gg, 256, GSMEM_BF>>>(hWi, hB, hC, b_in, hD, hE);
    // 4) cross-axis attention (both axes): (D,E) -> C (bf16 attx), A (bf16 atty)
    attn_kernel<<<2*BB*NHEADS, 320, ATTN2_SMEM>>>(hD, hE, hC, hA);
    // 5) final pointwise: W_out@(C+A) + 2*b_out + x residual
    dim3 go(HW/128, CC/128, BB);
    gemm_out<<<go, 256, GSMEM_OUT>>>(hWo, hC, hA, b_out, x, out);
}

// round 17
// speedup vs baseline: 1.1824x; 1.1824x over previous
#include <cuda_runtime.h>
#include <cuda_bf16.h>
#include <math.h>
#include <stdint.h>

#define BB     16
#define CC     256
#define HW     6400
#define NHEADS 8
#define CPH    32

// ---------------- scratch (static device globals; no allocation) -------------
__device__ float g_A[BB*CC*HW];
__device__ float g_B[BB*CC*HW];
__device__ float g_C[BB*CC*HW];
__device__ float g_D[BB*CC*HW];
__device__ float g_E[BB*CC*HW];
__device__ __nv_bfloat16 g_Wi[CC*CC];
__device__ __nv_bfloat16 g_Wo[CC*CC];

// ================= helpers ===================================================
__device__ __forceinline__ uint32_t smem_to_u32(const void* p) {
    uint32_t a;
    asm("{ .reg .u64 t; cvta.to.shared.u64 t, %1; cvt.u32.u64 %0, t; }" : "=r"(a) : "l"(p));
    return a;
}
__device__ __forceinline__ uint32_t pack2(float x, float y) {
    __nv_bfloat162 b = __float22bfloat162_rn(make_float2(x, y));
    return *(uint32_t*)&b;
}
__device__ __forceinline__ uint32_t hadd2u(uint32_t a, uint32_t b) {
    __nv_bfloat162 x = *(__nv_bfloat162*)&a, y = *(__nv_bfloat162*)&b;
    __nv_bfloat162 r = __hadd2(x, y);
    return *(uint32_t*)&r;
}
__device__ __forceinline__ void ldm_x4(uint32_t& r0, uint32_t& r1, uint32_t& r2, uint32_t& r3,
                                       uint32_t addr) {
    asm volatile("ldmatrix.sync.aligned.m8n8.x4.shared.b16 {%0,%1,%2,%3}, [%4];"
                 : "=r"(r0), "=r"(r1), "=r"(r2), "=r"(r3) : "r"(addr));
}
__device__ __forceinline__ void ldm_x4_t(uint32_t& r0, uint32_t& r1, uint32_t& r2, uint32_t& r3,
                                         uint32_t addr) {
    asm volatile("ldmatrix.sync.aligned.m8n8.x4.trans.shared.b16 {%0,%1,%2,%3}, [%4];"
                 : "=r"(r0), "=r"(r1), "=r"(r2), "=r"(r3) : "r"(addr));
}
__device__ __forceinline__ void ldm_x2(uint32_t& r0, uint32_t& r1, uint32_t addr) {
    asm volatile("ldmatrix.sync.aligned.m8n8.x2.shared.b16 {%0,%1}, [%2];"
                 : "=r"(r0), "=r"(r1) : "r"(addr));
}
__device__ __forceinline__ void ldm_x2_t(uint32_t& r0, uint32_t& r1, uint32_t addr) {
    asm volatile("ldmatrix.sync.aligned.m8n8.x2.trans.shared.b16 {%0,%1}, [%2];"
                 : "=r"(r0), "=r"(r1) : "r"(addr));
}
__device__ __forceinline__ void mma16816(float* d, const uint32_t* a, const uint32_t* b) {
    asm volatile("mma.sync.aligned.m16n8k16.row.col.f32.bf16.bf16.f32 "
                 "{%0,%1,%2,%3}, {%4,%5,%6,%7}, {%8,%9}, {%0,%1,%2,%3};"
                 : "+f"(d[0]), "+f"(d[1]), "+f"(d[2]), "+f"(d[3])
                 : "r"(a[0]), "r"(a[1]), "r"(a[2]), "r"(a[3]), "r"(b[0]), "r"(b[1]));
}
#define CP16(dst, src) asm volatile("cp.async.cg.shared.global [%0], [%1], 16;" :: "r"(dst), "l"(src))
#define CPCOMMIT()     asm volatile("cp.async.commit_group;" ::: "memory")
#define CPWAIT0()      asm volatile("cp.async.wait_group 0;" ::: "memory")

// ---------------- weight convert: fp32 -> bf16 (once) ------------------------
__global__ __launch_bounds__(256) void wconv_kernel(
    const float* __restrict__ w_in, const float* __restrict__ w_out,
    __nv_bfloat16* __restrict__ wi, __nv_bfloat16* __restrict__ wo)
{
    int i = blockIdx.x * 256 + threadIdx.x;
    float4 a = ((const float4*)w_in)[i];
    uint2 u;
    u.x = pack2(a.x, a.y); u.y = pack2(a.z, a.w);
    ((uint2*)wi)[i] = u;
    float4 b = ((const float4*)w_out)[i];
    uint2 v;
    v.x = pack2(b.x, b.y); v.y = pack2(b.z, b.w);
    ((uint2*)wo)[i] = v;
}

// ---------------- LayerNorm: float4 x 4-way channel split --------------------
// Lane-quad (4 consecutive threads) shares one 4-pixel group; each thread sums
// 64 channels, quad-reduces via shfl, then normalizes its own 64 channels.
__global__ __launch_bounds__(256) void ln_kernel(const float* __restrict__ x,
                                                 const float* __restrict__ gam,
                                                 const float* __restrict__ bet,
                                                 __nv_bfloat16* __restrict__ xn)
{
    int t  = blockIdx.x * 256 + threadIdx.x;   // 0..102399
    int g  = t >> 2;                           // pixel group 0..25599
    int q  = t & 3;                            // channel quarter
    int b  = g / 1600;
    int pl = (g - b * 1600) * 4;
    const float* xb = x + b * CC * HW + pl;
    const int c0 = q * 64;
    float4 s  = make_float4(0.f, 0.f, 0.f, 0.f);
    float4 s2 = make_float4(0.f, 0.f, 0.f, 0.f);
    #pragma unroll 8
    for (int c = c0; c < c0 + 64; c++) {
        float4 v = *(const float4*)(xb + c * HW);
        s.x += v.x; s.y += v.y; s.z += v.z; s.w += v.w;
        s2.x = fmaf(v.x, v.x, s2.x); s2.y = fmaf(v.y, v.y, s2.y);
        s2.z = fmaf(v.z, v.z, s2.z); s2.w = fmaf(v.w, v.w, s2.w);
    }
    #pragma unroll
    for (int m = 1; m <= 2; m <<= 1) {
        s.x  += __shfl_xor_sync(~0u, s.x,  m); s.y  += __shfl_xor_sync(~0u, s.y,  m);
        s.z  += __shfl_xor_sync(~0u, s.z,  m); s.w  += __shfl_xor_sync(~0u, s.w,  m);
        s2.x += __shfl_xor_sync(~0u, s2.x, m); s2.y += __shfl_xor_sync(~0u, s2.y, m);
        s2.z += __shfl_xor_sync(~0u, s2.z, m); s2.w += __shfl_xor_sync(~0u, s2.w, m);
    }
    const float ic = 1.f / CC;
    float4 mu = make_float4(s.x*ic, s.y*ic, s.z*ic, s.w*ic);
    float4 iv;
    iv.x = rsqrtf(s2.x*ic - mu.x*mu.x + 1e-5f);
    iv.y = rsqrtf(s2.y*ic - mu.y*mu.y + 1e-5f);
    iv.z = rsqrtf(s2.z*ic - mu.z*mu.z + 1e-5f);
    iv.w = rsqrtf(s2.w*ic - mu.w*mu.w + 1e-5f);
    __nv_bfloat16* ob = xn + b * CC * HW + pl;
    #pragma unroll 8
    for (int c = c0; c < c0 + 64; c++) {
        float4 v = *(const float4*)(xb + c * HW);
        float gm = gam[c], bt = bet[c];
        uint2 u;
        u.x = pack2((v.x - mu.x) * iv.x * gm + bt, (v.y - mu.y) * iv.y * gm + bt);
        u.y = pack2((v.z - mu.z) * iv.z * gm + bt, (v.w - mu.w) * iv.w * gm + bt);
        *(uint2*)(ob + c * HW) = u;
    }
}

// ---------------- fused depthwise, both dirs, bf16 HFMA2 2-wide --------------
__global__ __launch_bounds__(256) void dw_kernel(
    const __nv_bfloat16* __restrict__ xn,
    const float* __restrict__ wx7,  const float* __restrict__ bx7,
    const float* __restrict__ wx11, const float* __restrict__ bx11,
    const float* __restrict__ wx21, const float* __restrict__ bx21,
    const float* __restrict__ wy7,  const float* __restrict__ by7,
    const float* __restrict__ wy11, const float* __restrict__ by11,
    const float* __restrict__ wy21, const float* __restrict__ by21,
    __nv_bfloat16* __restrict__ dstX, __nv_bfloat16* __restrict__ dstY)
{
    __shared__ uint32_t pad[4000];
    __shared__ __nv_bfloat162 coef2[21];
    __shared__ float biasv;
    const int tid = threadIdx.x;
    const int dir = (blockIdx.x >= BB*CC) ? 1 : 0;
    const int bc  = blockIdx.x - dir * BB * CC;
    const int c   = bc & (CC - 1);
    const float* w7  = dir ? wy7  : wx7;
    const float* w11 = dir ? wy11 : wx11;
    const float* w21 = dir ? wy21 : wx21;
    for (int i = tid; i < 4000; i += 256) pad[i] = 0;
    if (tid < 21) {
        int t = tid - 10;
        float v = w21[c*21 + t + 10];
        if (t >= -5 && t <= 5) v += w11[c*11 + t + 5];
        if (t >= -3 && t <= 3) v += w7 [c*7  + t + 3];
        coef2[tid] = __float2bfloat162_rn(v);
    }
    if (tid == 0) {
        biasv = (dir ? (by7[c] + by11[c] + by21[c])
                     : (bx7[c] + bx11[c] + bx21[c]));
    }
    __syncthreads();
    const uint32_t* src32 = (const uint32_t*)(xn + bc * HW);
    if (dir == 0) {
        for (int i = tid; i < 1600; i += 256) {
            int h2 = i / 40, wp2 = i - h2 * 40;
            uint32_t a01 = src32[(2*h2)*40 + wp2];
            uint32_t b01 = src32[(2*h2+1)*40 + wp2];
            pad[h2*100 + 10 + 2*wp2] = __byte_perm(a01, b01, 0x5410);
            pad[h2*100 + 11 + 2*wp2] = __byte_perm(a01, b01, 0x7632);
        }
    } else {
        for (int i = tid; i < 3200; i += 256) {
            int h = i / 40, w2 = i - h * 40;
            pad[(h + 10)*40 + w2] = src32[i];
        }
    }
    __syncthreads();
    const __nv_bfloat162 bias2 = __float2bfloat162_rn(biasv);
    const __nv_bfloat162 z2    = __float2bfloat162_rn(0.f);
    uint32_t* dst32 = (uint32_t*)((dir ? dstY : dstX) + bc * HW);
    for (int i = tid; i < 1600; i += 256) {
        int h2 = i / 40, w2 = i - h2 * 40;
        uint32_t win[22];
        if (dir == 0) {
            #pragma unroll
            for (int t = 0; t < 22; t++) win[t] = pad[h2*100 + 2*w2 + t];
        } else {
            #pragma unroll
            for (int t = 0; t < 22; t++) win[t] = pad[(2*h2 + t)*40 + w2];
        }
        __nv_bfloat162 ae = bias2, ao = z2, be = bias2, bo = z2;
        #pragma unroll
        for (int t = 0; t < 21; t++) {
            __nv_bfloat162 w0 = *(__nv_bfloat162*)&win[t];
            __nv_bfloat162 w1 = *(__nv_bfloat162*)&win[t + 1];
            if (t & 1) { ao = __hfma2(coef2[t], w0, ao); bo = __hfma2(coef2[t], w1, bo); }
            else       { ae = __hfma2(coef2[t], w0, ae); be = __hfma2(coef2[t], w1, be); }
        }
        __nv_bfloat162 A2 = __hadd2(ae, ao);
        __nv_bfloat162 B2 = __hadd2(be, bo);
        uint32_t uA = *(uint32_t*)&A2, uB = *(uint32_t*)&B2;
        if (dir == 0) {
            dst32[(2*h2)*40 + w2]   = __byte_perm(uA, uB, 0x5410);
            dst32[(2*h2+1)*40 + w2] = __byte_perm(uA, uB, 0x7632);
        } else {
            dst32[(2*h2)*40 + w2]   = uA;
            dst32[(2*h2+1)*40 + w2] = uB;
        }
    }
}

// ====== bf16 GEMM, cp.async weights + double-buffered A, merged inputs =======
#define GSMEM_BF (64*1024 + 2*16*1024)

__global__ __launch_bounds__(256) void gemm_bf(
    const __nv_bfloat16* __restrict__ Wb,
    const __nv_bfloat16* __restrict__ Xa, const __nv_bfloat16* __restrict__ Xb,
    const float* __restrict__ bias,
    __nv_bfloat16* __restrict__ Oa, __nv_bfloat16* __restrict__ Ob)
{
    extern __shared__ char smem[];
    char* Bs = smem;
    const uint32_t Bs32 = smem_to_u32(Bs);
    const uint32_t As32 = smem_to_u32(smem + 65536);
    const int tid = threadIdx.x, wid = tid >> 5, lane = tid & 31;
    const int wm = wid >> 1, wn = wid & 1;
    const int p0 = blockIdx.x * 128, o0 = blockIdx.y * 128;
    const int sel = blockIdx.z >> 4;
    const long xbase = (long)(blockIdx.z & 15) * (CC * HW);
    const __nv_bfloat16* X = sel ? Xb : Xa;
    __nv_bfloat16* out     = sel ? Ob : Oa;

    #pragma unroll
    for (int it = 0; it < 16; it++) {
        int idx = tid + it * 256;
        int n = idx >> 5, kc = idx & 31;
        CP16(Bs32 + n * 512 + ((kc ^ (n & 7)) << 4), Wb + (o0 + n) * CC + kc * 8);
    }

    float acc[2][8][4];
    #pragma unroll
    for (int i = 0; i < 2; i++)
        #pragma unroll
        for (int j = 0; j < 8; j++)
            #pragma unroll
            for (int t = 0; t < 4; t++) acc[i][j][t] = 0.f;

    auto fillA = [&](int ch, int buf) {
        #pragma unroll
        for (int it = 0; it < 4; it++) {
            int idx = tid + it * 256;
            int k = idx >> 4, cm = idx & 15;
            const __nv_bfloat16* src = X + xbase + (long)(ch * 64 + k) * HW + p0 + cm * 8;
            uint32_t dst = As32 + buf * 16384 + k * 256 + ((cm ^ (k & 7)) << 4);
            CP16(dst, src);
        }
        CPCOMMIT();
    };

    fillA(0, 0);
    for (int ch = 0; ch < 4; ch++) {
        CPWAIT0();
        __syncthreads();
        if (ch < 3) fillA(ch + 1, (ch + 1) & 1);
        const uint32_t Ab = As32 + (ch & 1) * 16384;
        #pragma unroll
        for (int ks = 0; ks < 4; ks++) {
            uint32_t a[2][4];
            #pragma unroll
            for (int am = 0; am < 2; am++) {
                int krow = ks * 16 + (lane & 7) + ((lane >> 4) << 3);
                int cm   = (wm * 32 + am * 16) / 8 + ((lane >> 3) & 1);
                ldm_x4_t(a[am][0], a[am][1], a[am][2], a[am][3],
                         Ab + krow * 256 + ((cm ^ (krow & 7)) << 4));
            }
            uint32_t b[4][4];
            #pragma unroll
            for (int bp = 0; bp < 4; bp++) {
                int n  = wn * 64 + bp * 16 + (lane & 15);
                int kc = ch * 8 + ks * 2 + (lane >> 4);
                ldm_x4(b[bp][0], b[bp][1], b[bp][2], b[bp][3],
                       Bs32 + n * 512 + ((kc ^ (n & 7)) << 4));
            }
            #pragma unroll
            for (int am = 0; am < 2; am++)
                #pragma unroll
                for (int an = 0; an < 8; an++) {
                    uint32_t bb[2] = { b[an >> 1][an & 1], b[an >> 1][(an & 1) + 2] };
                    mma16816(acc[am][an], a[am], bb);
                }
        }
    }

    __syncthreads();
    #pragma unroll
    for (int am = 0; am < 2; am++) {
        int m = wm * 32 + am * 16 + (lane >> 2);
        #pragma unroll
        for (int an = 0; an < 8; an++) {
            int nl = wn * 64 + an * 8 + (lane & 3) * 2;
            float b0 = bias[o0 + nl], b1 = bias[o0 + nl + 1];
            *(__nv_bfloat16*)(Bs + nl * 256 + m * 2)             = __float2bfloat16(acc[am][an][0] + b0);
            *(__nv_bfloat16*)(Bs + (nl + 1) * 256 + m * 2)       = __float2bfloat16(acc[am][an][1] + b1);
            *(__nv_bfloat16*)(Bs + nl * 256 + (m + 8) * 2)       = __float2bfloat16(acc[am][an][2] + b0);
            *(__nv_bfloat16*)(Bs + (nl + 1) * 256 + (m + 8) * 2) = __float2bfloat16(acc[am][an][3] + b1);
        }
    }
    __syncthreads();
    #pragma unroll
    for (int it = 0; it < 32; it++) {
        int idx = tid + it * 256;
        int n = idx >> 6, mu = idx & 63;
        uint32_t u = *(uint32_t*)(Bs + n * 256 + mu * 4);
        *(uint32_t*)(out + xbase + (long)(o0 + n) * HW + p0 + 2 * mu) = u;
    }
}

// ====== final GEMM: out = W@(X+X2) + 2b + resid, cp.async weights ============
#define GSMEM_OUT (64*1024 + 32*1024)

__global__ __launch_bounds__(256) void gemm_out(
    const __nv_bfloat16* __restrict__ Wb, const __nv_bfloat16* __restrict__ X,
    const __nv_bfloat16* __restrict__ X2,
    const float* __restrict__ bias, const float* __restrict__ resid,
    float* __restrict__ out)
{
    extern __shared__ char smem[];
    char* Bs = smem;
    const uint32_t Bs32 = smem_to_u32(Bs);
    const uint32_t As32 = smem_to_u32(smem + 65536);
    const int tid = threadIdx.x, wid = tid >> 5, lane = tid & 31;
    const int wm = wid >> 1, wn = wid & 1;
    const int p0 = blockIdx.x * 128, o0 = blockIdx.y * 128;
    const long xbase = (long)blockIdx.z * (CC * HW);

    #pragma unroll
    for (int it = 0; it < 16; it++) {
        int idx = tid + it * 256;
        int n = idx >> 5, kc = idx & 31;
        CP16(Bs32 + n * 512 + ((kc ^ (n & 7)) << 4), Wb + (o0 + n) * CC + kc * 8);
    }

    float acc[2][8][4];
    #pragma unroll
    for (int i = 0; i < 2; i++)
        #pragma unroll
        for (int j = 0; j < 8; j++)
            #pragma unroll
            for (int t = 0; t < 4; t++) acc[i][j][t] = 0.f;

    auto fillA = [&](int ch, int buf) {
        #pragma unroll
        for (int it = 0; it < 2; it++) {
            int idx = tid + it * 256;
            int k = idx >> 4, cm = idx & 15;
            long off = xbase + (long)(ch * 32 + k) * HW + p0 + cm * 8;
            uint32_t dst = As32 + buf * 16384 + k * 256 + ((cm ^ (k & 7)) << 4);
            CP16(dst, X + off);
            CP16(dst + 8192, X2 + off);
        }
        CPCOMMIT();
    };

    fillA(0, 0);
    for (int ch = 0; ch < 8; ch++) {
        CPWAIT0();
        __syncthreads();
        if (ch < 7) fillA(ch + 1, (ch + 1) & 1);
        const uint32_t Ab = As32 + (ch & 1) * 16384;
        #pragma unroll
        for (int ks = 0; ks < 2; ks++) {
            uint32_t a[2][4];
            #pragma unroll
            for (int am = 0; am < 2; am++) {
                int krow = ks * 16 + (lane & 7) + ((lane >> 4) << 3);
                int cm   = (wm * 32 + am * 16) / 8 + ((lane >> 3) & 1);
                uint32_t addr = Ab + krow * 256 + ((cm ^ (krow & 7)) << 4);
                uint32_t p0r, p1r, p2r, p3r, q0r, q1r, q2r, q3r;
                ldm_x4_t(p0r, p1r, p2r, p3r, addr);
                ldm_x4_t(q0r, q1r, q2r, q3r, addr + 8192);
                a[am][0] = hadd2u(p0r, q0r);
                a[am][1] = hadd2u(p1r, q1r);
                a[am][2] = hadd2u(p2r, q2r);
                a[am][3] = hadd2u(p3r, q3r);
            }
            uint32_t b[4][4];
            #pragma unroll
            for (int bp = 0; bp < 4; bp++) {
                int n  = wn * 64 + bp * 16 + (lane & 15);
                int kc = ch * 4 + ks * 2 + (lane >> 4);
                ldm_x4(b[bp][0], b[bp][1], b[bp][2], b[bp][3],
                       Bs32 + n * 512 + ((kc ^ (n & 7)) << 4));
            }
            #pragma unroll
            for (int am = 0; am < 2; am++)
                #pragma unroll
                for (int an = 0; an < 8; an++) {
                    uint32_t bb[2] = { b[an >> 1][an & 1], b[an >> 1][(an & 1) + 2] };
                    mma16816(acc[am][an], a[am], bb);
                }
        }
    }

    #pragma unroll
    for (int am = 0; am < 2; am++) {
        int m = wm * 32 + am * 16 + (lane >> 2);
        #pragma unroll
        for (int an = 0; an < 8; an++) {
            int n = o0 + wn * 64 + an * 8 + (lane & 3) * 2;
            float b0 = bias[n] * 2.f, b1 = bias[n + 1] * 2.f;
            long a00 = xbase + (long)n * HW + p0 + m;
            out[a00]          = acc[am][an][0] + b0 + resid[a00];
            out[a00 + HW]     = acc[am][an][1] + b1 + resid[a00 + HW];
            out[a00 + 8]      = acc[am][an][2] + b0 + resid[a00 + 8];
            out[a00 + HW + 8] = acc[am][an][3] + b1 + resid[a00 + HW + 8];
        }
    }
}

// ======== cross-axis attention: native-layout cp.async staging ===============
#define FPB 176
#define OFF_TK 28160
#define OFF_PS 56320
#define OFF_GM 70400
#define OFF_RQ 96320
#define OFF_RK 96640
#define OFF_PART 96960
#define ATTN2_SMEM 98240

__global__ __launch_bounds__(320, 2) void attn_kernel(
    const __nv_bfloat16* __restrict__ fx, const __nv_bfloat16* __restrict__ fy,
    __nv_bfloat16* __restrict__ outx, __nv_bfloat16* __restrict__ outy)
{
    extern __shared__ char sm2[];
    float* Gm = (float*)(sm2 + OFF_GM);
    float* rq = (float*)(sm2 + OFF_RQ);
    float* rk = (float*)(sm2 + OFF_RK);
    float* part = (float*)(sm2 + OFF_PART);
    const uint32_t tq32 = smem_to_u32(sm2);
    const uint32_t tk32 = tq32 + OFF_TK;
    const uint32_t ps32 = tq32 + OFF_PS;

    const int axis = blockIdx.x >> 7;
    const int bh   = blockIdx.x & 127;
    const int cbase = (bh >> 3) * (CC*HW) + (bh & 7) * (CPH*HW);
    const __nv_bfloat16* Qb = (axis ? fx : fy) + cbase;
    const __nv_bfloat16* Kb = (axis ? fy : fx) + cbase;
    __nv_bfloat16* outb     = (axis ? outy : outx) + cbase;
    const int tid  = threadIdx.x;
    const int wid  = tid >> 5, lane = tid & 31;
    const int mt   = wid >> 1, nh = wid & 1;

    auto fill = [&](int c, int b) {
        const __nv_bfloat16* qc = Qb + c*HW;
        const __nv_bfloat16* kc = Kb + c*HW;
        uint32_t dq = tq32 + b * 14080;
        uint32_t dk = tk32 + b * 14080;
        #pragma unroll
        for (int it = 0; it < 5; it++) {
            int idx = tid + it * 320;
            int pl  = (idx >= 800);
            int j   = idx - pl * 800;
            int r = j / 10, cj = j - r * 10;
            const __nv_bfloat16* s = (pl ? kc : qc) + r * 80 + cj * 8;
            uint32_t d = (pl ? dk : dq) + r * FPB + cj * 16;
            CP16(d, s);
        }
        CPCOMMIT();
    };

    auto loadB = [&](uint32_t tb, int ks, bool tr, uint32_t* bA, uint32_t* bB, uint32_t* bC) {
        if (!tr) {
            {
                int row = nh*40 + (lane & 15);
                ldm_x4(bA[0], bA[1], bA[2], bA[3], tb + row*FPB + ks*32 + ((lane >> 4) << 4));
            }
            {
                int row = nh*40 + 16 + (lane & 15);
                ldm_x4(bB[0], bB[1], bB[2], bB[3], tb + row*FPB + ks*32 + ((lane >> 4) << 4));
            }
            {
                int row = nh*40 + 32 + (lane & 7);
                ldm_x2(bC[0], bC[1], tb + row*FPB + ks*32 + (((lane >> 3) & 1) << 4));
            }
        } else {
            int krow = ks*16 + (lane & 7) + ((lane >> 4) << 3);
            {
                int nc = nh*5 + ((lane >> 3) & 1);
                ldm_x4_t(bA[0], bA[1], bA[2], bA[3], tb + krow*FPB + (nc << 4));
            }
            {
                int nc = nh*5 + 2 + ((lane >> 3) & 1);
                ldm_x4_t(bB[0], bB[1], bB[2], bB[3], tb + krow*FPB + (nc << 4));
            }
            {
                int kr2 = ks*16 + (lane & 7) + (((lane >> 3) & 1) << 3);
                int nc = nh*5 + 4;
                ldm_x2_t(bC[0], bC[1], tb + kr2*FPB + (nc << 4));
            }
        }
    };

    float acc[5][4];
    #pragma unroll
    for (int j = 0; j < 5; j++)
        #pragma unroll
        for (int t = 0; t < 4; t++) acc[j][t] = 0.f;
    float nss = 0.f;

    // ================= Phase 1: raw Gram + fused sumsq (all 320 threads) =====
    const int seqp = tid >> 1;
    const int shalf = tid & 1;
    fill(0, 0);
    for (int c = 0; c < CPH; c++) {
        const int b = c & 1;
        CPWAIT0();
        __syncthreads();
        if (c < CPH-1) fill(c + 1, b ^ 1);
        const uint32_t qb = tq32 + b * 14080;
        const uint32_t kb = tk32 + b * 14080;
        {
            const char* pb = (char*)sm2 + ((seqp < 80) ? b*14080 : OFF_TK + b*14080);
            int sp = (seqp < 80) ? seqp : seqp - 80;
            float s = 0.f;
            if (axis == 0) {
                const char* rowp = pb + sp * FPB + shalf * 80;
                #pragma unroll
                for (int u = 0; u < 20; u++) {
                    __nv_bfloat162 h2 = *(const __nv_bfloat162*)(rowp + 4*u);
                    float2 f2 = __bfloat1622float2(h2);
                    s = fmaf(f2.x, f2.x, fmaf(f2.y, f2.y, s));
                }
            } else {
                #pragma unroll 8
                for (int rr = shalf*40; rr < shalf*40 + 40; rr++) {
                    float v = __bfloat162float(*(const __nv_bfloat16*)(pb + rr*FPB + sp*2));
                    s = fmaf(v, v, s);
                }
            }
            nss += s;
        }
        #pragma unroll
        for (int ks = 0; ks < 5; ks++) {
            uint32_t a[4];
            if (axis == 0) {
                int row = mt*16 + (lane & 15);
                ldm_x4(a[0], a[1], a[2], a[3], qb + row*FPB + ks*32 + ((lane >> 4) << 4));
            } else {
                int krow = ks*16 + (lane & 7) + ((lane >> 4) << 3);
                int mc   = mt*2 + ((lane >> 3) & 1);
                ldm_x4_t(a[0], a[1], a[2], a[3], qb + krow*FPB + (mc << 4));
            }
            uint32_t bA[4], bB[4], bC[2];
            loadB(kb, ks, axis == 1, bA, bB, bC);
            { uint32_t bb[2] = { bA[0], bA[2] }; mma16816(acc[0], a, bb); }
            { uint32_t bb[2] = { bA[1], bA[3] }; mma16816(acc[1], a, bb); }
            { uint32_t bb[2] = { bB[0], bB[2] }; mma16816(acc[2], a, bb); }
            { uint32_t bb[2] = { bB[1], bB[3] }; mma16816(acc[3], a, bb); }
            { uint32_t bb[2] = { bC[0], bC[1] }; mma16816(acc[4], a, bb); }
        }
    }
    __syncthreads();
    part[tid] = nss;
    __syncthreads();
    if (tid < 160) {
        float s = part[2*tid] + part[2*tid + 1];
        float inv = 1.f / fmaxf(sqrtf(s), 1e-12f);
        if (tid < 80) rq[tid] = inv; else rk[tid - 80] = inv;
    }
    __syncthreads();
    {
        int row  = mt*16 + (lane >> 2);
        int colb = nh*40 + (lane & 3) * 2;
        float r0 = rq[row], r1 = rq[row + 8];
        #pragma unroll
        for (int j = 0; j < 5; j++) {
            int col = colb + j*8;
            float k0 = rk[col], k1 = rk[col + 1];
            Gm[row*81 + col]       = acc[j][0] * r0 * k0;
            Gm[row*81 + col + 1]   = acc[j][1] * r0 * k1;
            Gm[(row+8)*81 + col]   = acc[j][2] * r1 * k0;
            Gm[(row+8)*81 + col+1] = acc[j][3] * r1 * k1;
        }
    }
    __syncthreads();
    // ================= Phase 2: softmax rows =================
    if (tid < 80) {
        float* row = Gm + tid*81;
        float mx = -3.0e38f;
        for (int m = 0; m < 80; m++) mx = fmaxf(mx, row[m]);
        float s = 0.f;
        for (int m = 0; m < 80; m++) { float e = expf(row[m] - mx); row[m] = e; s += e; }
        float is = 1.f / s;
        for (int m = 0; m < 80; m++) row[m] *= is;
    }
    __syncthreads();
    #pragma unroll
    for (int it = 0; it < 10; it++) {
        int p = tid + it * 320;
        int n = p / 40, mp = p - n * 40;
        *(uint32_t*)(sm2 + OFF_PS + n*FPB + 4*mp) = pack2(Gm[n*81 + 2*mp], Gm[n*81 + 2*mp + 1]);
    }
    __syncthreads();
    uint32_t aP[5][4];
    #pragma unroll
    for (int ks = 0; ks < 5; ks++) {
        int row = mt*16 + (lane & 15);
        ldm_x4(aP[ks][0], aP[ks][1], aP[ks][2], aP[ks][3],
               ps32 + row*FPB + ks*32 + ((lane >> 4) << 4));
    }

    // ================= Phase 3: out = P@V + q*rq =================
    fill(0, 0);
    for (int c = 0; c < CPH; c++) {
        const int b = c & 1;
        CPWAIT0();
        __syncthreads();
        if (c < CPH-1) fill(c + 1, b ^ 1);
        const uint32_t kb = tk32 + b * 14080;
        const char* qsm = sm2 + b * 14080;
        float o[5][4];
        #pragma unroll
        for (int j = 0; j < 5; j++)
            #pragma unroll
            for (int t = 0; t < 4; t++) o[j][t] = 0.f;
        #pragma unroll
        for (int ks = 0; ks < 5; ks++) {
            uint32_t bA[4], bB[4], bC[2];
            loadB(kb, ks, axis == 0, bA, bB, bC);
            { uint32_t bb[2] = { bA[0], bA[2] }; mma16816(o[0], aP[ks], bb); }
            { uint32_t bb[2] = { bA[1], bA[3] }; mma16816(o[1], aP[ks], bb); }
            { uint32_t bb[2] = { bB[0], bB[2] }; mma16816(o[2], aP[ks], bb); }
            { uint32_t bb[2] = { bB[1], bB[3] }; mma16816(o[3], aP[ks], bb); }
            { uint32_t bb[2] = { bC[0], bC[1] }; mma16816(o[4], aP[ks], bb); }
        }
        __nv_bfloat16* ob = outb + c*HW;
        int row  = mt*16 + (lane >> 2);
        int colb = nh*40 + (lane & 3) * 2;
        #pragma unroll
        for (int j = 0; j < 5; j++) {
            int col = colb + j*8;
            #pragma unroll
            for (int half = 0; half < 2; half++) {
                int rr = row + 8*half;
                float rqi = rq[rr];
                float q0, q1;
                if (axis == 0) {
                    __nv_bfloat162 q2 = *(const __nv_bfloat162*)(qsm + rr*FPB + col*2);
                    float2 qf = __bfloat1622float2(q2);
                    q0 = qf.x; q1 = qf.y;
                } else {
                    q0 = __bfloat162float(*(const __nv_bfloat16*)(qsm + col*FPB + rr*2));
                    q1 = __bfloat162float(*(const __nv_bfloat16*)(qsm + (col+1)*FPB + rr*2));
                }
                float v0 = o[j][2*half]     + q0 * rqi;
                float v1 = o[j][2*half + 1] + q1 * rqi;
                if (axis == 0) {
                    *(uint32_t*)(ob + rr*80 + col) = pack2(v0, v1);
                } else {
                    ob[col*80 + rr]       = __float2bfloat16(v0);
                    ob[(col+1)*80 + rr]   = __float2bfloat16(v1);
                }
            }
        }
    }
}

// ---------------- launch -----------------------------------------------------
extern "C" void kernel_launch(void* const* d_in, const int* in_sizes, int n_in,
                              void* d_out, int out_size)
{
    const float* x    = (const float*)d_in[0];
    const float* ln_g = (const float*)d_in[1];
    const float* ln_b = (const float*)d_in[2];
    const float* w_in = (const float*)d_in[3];
    const float* b_in = (const float*)d_in[4];
    const float* w_out= (const float*)d_in[5];
    const float* b_out= (const float*)d_in[6];
    const float* wx7  = (const float*)d_in[7];
    const float* bx7  = (const float*)d_in[8];
    const float* wx11 = (const float*)d_in[9];
    const float* bx11 = (const float*)d_in[10];
    const float* wx21 = (const float*)d_in[11];
    const float* bx21 = (const float*)d_in[12];
    const float* wy7  = (const float*)d_in[13];
    const float* by7  = (const float*)d_in[14];
    const float* wy11 = (const float*)d_in[15];
    const float* by11 = (const float*)d_in[16];
    const float* wy21 = (const float*)d_in[17];
    const float* by21 = (const float*)d_in[18];
    float* out = (float*)d_out;

    float *pA, *pB, *pC, *pD, *pE;
    cudaGetSymbolAddress((void**)&pA, g_A);
    cudaGetSymbolAddress((void**)&pB, g_B);
    cudaGetSymbolAddress((void**)&pC, g_C);
    cudaGetSymbolAddress((void**)&pD, g_D);
    cudaGetSymbolAddress((void**)&pE, g_E);
    __nv_bfloat16 *hWi, *hWo;
    cudaGetSymbolAddress((void**)&hWi, g_Wi);
    cudaGetSymbolAddress((void**)&hWo, g_Wo);
    __nv_bfloat16* hA = (__nv_bfloat16*)pA;
    __nv_bfloat16* hB = (__nv_bfloat16*)pB;
    __nv_bfloat16* hC = (__nv_bfloat16*)pC;
    __nv_bfloat16* hD = (__nv_bfloat16*)pD;
    __nv_bfloat16* hE = (__nv_bfloat16*)pE;

    cudaFuncSetAttribute(attn_kernel, cudaFuncAttributeMaxDynamicSharedMemorySize, ATTN2_SMEM);
    cudaFuncSetAttribute(gemm_bf,  cudaFuncAttributeMaxDynamicSharedMemorySize, GSMEM_BF);
    cudaFuncSetAttribute(gemm_out, cudaFuncAttributeMaxDynamicSharedMemorySize, GSMEM_OUT);

    // 0) weights fp32 -> bf16 (tiny)
    wconv_kernel<<<64, 256>>>(w_in, w_out, hWi, hWo);
    // 1) LayerNorm: x -> A (bf16 xn); 102400 threads, float4, quad-split channels
    ln_kernel<<<400, 256>>>(x, ln_g, ln_b, hA);
    // 2) depthwise (both dirs): A -> B (bf16 sx), C (bf16 sy)
    dw_kernel<<<2*BB*CC, 256>>>(hA, wx7, bx7, wx11, bx11, wx21, bx21,
                                wy7, by7, wy11, by11, wy21, by21, hB, hC);
    // 3) pointwise w_in merged: B->D (fx), C->E (fy)
    dim3 gg(HW/128, CC/128, 2*BB);
    gemm_bf<<<gg, 256, GSMEM_BF>>>(hWi, hB, hC, b_in, hD, hE);
    // 4) cross-axis attention (both axes): (D,E) -> C (bf16 attx), A (bf16 atty)
    attn_kernel<<<2*BB*NHEADS, 320, ATTN2_SMEM>>>(hD, hE, hC, hA);
    // 5) final pointwise: W_out@(C+A) + 2*b_out + x residual
    dim3 go(HW/128, CC/128, BB);
    gemm_out<<<go, 256, GSMEM_OUT>>>(hWo, hC, hA, b_out, x, out);
}